// round 5
// baseline (speedup 1.0000x reference)
#include <cuda_runtime.h>
#include <math.h>

#define BB 64
#define SS 512
#define FF 512
#define HH 1024
#define G3 3072
#define NBLOCKS 128
#define NT 512
#define WSM_FLOATS (1024 * 48)      // resident W slice: [k=1024][48 gate-cols]
#define SCR_STRIDE 25               // odd stride -> spread banks
#define SCR_OFF WSM_FLOATS

// Scratch for input-side gates gx = x @ W_ih + bias : [B*S, 3H] fp32
__device__ float g_gx[(size_t)BB * SS * G3];

// Software grid barrier (generation counter — replay-safe)
__device__ unsigned int g_count = 0;
__device__ volatile unsigned int g_gen = 0;

typedef unsigned long long u64t;

// ---------------- f32x2 packed-FMA helpers ----------------
__device__ __forceinline__ u64t pack2(float lo, float hi) {
    u64t r; asm("mov.b64 %0, {%1, %2};" : "=l"(r) : "f"(lo), "f"(hi)); return r;
}
__device__ __forceinline__ void unpack2(u64t v, float& lo, float& hi) {
    asm("mov.b64 {%0, %1}, %2;" : "=f"(lo), "=f"(hi) : "l"(v));
}
__device__ __forceinline__ void fma2(u64t& d, u64t a, u64t b) {
    asm("fma.rn.f32x2 %0, %1, %2, %0;" : "+l"(d) : "l"(a), "l"(b));
}

// ---------------- cp.async helpers ----------------
__device__ __forceinline__ void cp16(unsigned int dst, const void* src) {
    asm volatile("cp.async.ca.shared.global [%0], [%1], 16;" :: "r"(dst), "l"(src) : "memory");
}
__device__ __forceinline__ void cp_commit() { asm volatile("cp.async.commit_group;" ::: "memory"); }
template<int N> __device__ __forceinline__ void cp_wait() {
    asm volatile("cp.async.wait_group %0;" :: "n"(N) : "memory");
}
__device__ __forceinline__ unsigned int smem_u32(const void* p) {
    return (unsigned int)__cvta_generic_to_shared(p);
}

__device__ __forceinline__ float gate_fn(float az, float ar, float ge, float ae, float ho) {
    float z   = 1.0f / (1.0f + expf(-az));
    float r   = 1.0f / (1.0f + expf(-ar));
    float eta = tanhf(ge + r * tanhf(ae));
    return z * ho + (1.0f - z) * eta;
}

// ---------------------------------------------------------------------------
// Kernel 1: input GEMM  g_gx = x @ W_ih + bias.  M=32768, K=512, N=3072.
// ---------------------------------------------------------------------------
__global__ __launch_bounds__(256, 2) void gemm_ih(const float* __restrict__ A,
                                                  const float* __restrict__ Bw,
                                                  const float* __restrict__ bias) {
    __shared__ float As[16][132];
    __shared__ float Bs[16][128];

    const int K = FF, N = G3;
    const int bm = blockIdx.y * 128;
    const int bn = blockIdx.x * 128;
    const int tid = threadIdx.x;
    const int tr = tid >> 4;
    const int tc = tid & 15;

    u64t acc2[8][4];
#pragma unroll
    for (int i = 0; i < 8; ++i)
#pragma unroll
        for (int j = 0; j < 4; ++j) acc2[i][j] = 0ULL;

    for (int k0 = 0; k0 < K; k0 += 16) {
#pragma unroll
        for (int i = 0; i < 2; ++i) {
            int f = tid + i * 256;
            int ar = f >> 2, ac4 = f & 3;
            float4 av = *(const float4*)(A + (size_t)(bm + ar) * K + k0 + ac4 * 4);
            As[ac4 * 4 + 0][ar] = av.x;
            As[ac4 * 4 + 1][ar] = av.y;
            As[ac4 * 4 + 2][ar] = av.z;
            As[ac4 * 4 + 3][ar] = av.w;
            int br = f >> 5, bc4 = f & 31;
            *(float4*)(&Bs[br][bc4 * 4]) =
                *(const float4*)(Bw + (size_t)(k0 + br) * N + bn + bc4 * 4);
        }
        __syncthreads();
#pragma unroll
        for (int kk = 0; kk < 16; ++kk) {
            float a[8];
            *(float4*)(a)     = *(const float4*)(&As[kk][tr * 8]);
            *(float4*)(a + 4) = *(const float4*)(&As[kk][tr * 8 + 4]);
            ulonglong2 bq0 = *(const ulonglong2*)(&Bs[kk][tc * 8]);
            ulonglong2 bq1 = *(const ulonglong2*)(&Bs[kk][tc * 8 + 4]);
#pragma unroll
            for (int i = 0; i < 8; ++i) {
                u64t ai = pack2(a[i], a[i]);
                fma2(acc2[i][0], ai, bq0.x);
                fma2(acc2[i][1], ai, bq0.y);
                fma2(acc2[i][2], ai, bq1.x);
                fma2(acc2[i][3], ai, bq1.y);
            }
        }
        __syncthreads();
    }

#pragma unroll
    for (int i = 0; i < 8; ++i) {
        int row = bm + tr * 8 + i;
        float o[8];
        unpack2(acc2[i][0], o[0], o[1]);
        unpack2(acc2[i][1], o[2], o[3]);
        unpack2(acc2[i][2], o[4], o[5]);
        unpack2(acc2[i][3], o[6], o[7]);
#pragma unroll
        for (int j = 0; j < 8; j += 4) {
            int col = bn + tc * 8 + j;
            float4 bv = *(const float4*)(bias + col);
            float4 ov;
            ov.x = o[j + 0] + bv.x;
            ov.y = o[j + 1] + bv.y;
            ov.z = o[j + 2] + bv.z;
            ov.w = o[j + 3] + bv.w;
            *(float4*)(g_gx + (size_t)row * N + col) = ov;
        }
    }
}

// ---------------------------------------------------------------------------
// Kernel 2: persistent GRU scan. 128 CTAs x 512 threads, 512 steps.
//   W_hh slice [1024 x 48] RESIDENT in smem for the whole kernel (loaded once).
//   h_{t-1} streamed from gmem with register double-buffering.
//   8-way K split across warp groups; f32x2 FMA; 2-stage smem tree reduction.
// ---------------------------------------------------------------------------
__global__ __launch_bounds__(NT, 1) void gru_scan(const float* __restrict__ whh,
                                                  float* __restrict__ out) {
    extern __shared__ float smem[];
    float* wsm = smem;                 // [1024][48]
    float* scr = smem + SCR_OFF;       // [4][64][SCR_STRIDE]

    const int bid = blockIdx.x;
    const int mt = bid >> 6;                // 0..1  (batch-row half)
    const int jt = bid & 63;                // 0..63 (hidden col tile)
    const int m0 = mt * 32;
    const int jbase = jt * 16;
    const int tid = threadIdx.x;
    const int kq = tid >> 6;                // 0..7 K octant (128 k each)
    const int local = tid & 63;
    const int mp = local & 15;              // row pair -> rows 2mp, 2mp+1
    const int jq = local >> 4;              // 0..3 -> cols jq*4..+4

    // ---- one-time W_hh slice load: whh[k][g*1024 + jbase + c] -> wsm[k][g*16 + c]
    {
        const unsigned int wsu = smem_u32(wsm);
#pragma unroll
        for (int i = 0; i < 24; ++i) {
            int idx = tid + NT * i;              // 0..12287
            int k = idx / 12;
            int sub = idx - k * 12;
            int g = sub >> 2, c4 = sub & 3;
            cp16(wsu + (unsigned)(k * 48 + g * 16 + c4 * 4) * 4u,
                 whh + (size_t)k * G3 + g * HH + jbase + c4 * 4);
        }
        cp_commit();
        cp_wait<0>();
        __syncthreads();
    }

    // gate-phase mapping: one output per thread
    const int gm = tid >> 4;                // 0..31 local row
    const int gj = tid & 15;                // 0..15 local col
    const int glocal = (gj >> 2) * 16 + (gm >> 1);
    const int gr_ = gm & 1;                 // row parity within owner
    const int gc_ = gj & 3;                 // col within quad

    const float* wb_base = wsm + (size_t)(kq * 128) * 48 + jq * 4;

    for (int t = 0; t < SS; ++t) {
        // ---- prefetch gate-phase inputs ----
        const float* gp = g_gx + ((size_t)(m0 + gm) * SS + t) * G3 + jbase + gj;
        float gz = gp[0], grv = gp[HH], gev = gp[2 * HH];
        float hov = 0.0f;
        if (t > 0)
            hov = out[((size_t)(m0 + gm) * SS + (t - 1)) * HH + jbase + gj];

        if (t > 0) {
            const float* h0 = out + ((size_t)(m0 + 2 * mp) * SS + (t - 1)) * HH + kq * 128;
            const float* h1 = h0 + (size_t)SS * HH;

            u64t acc[12];
#pragma unroll
            for (int i = 0; i < 12; ++i) acc[i] = 0ULL;

            float4 hb0[2][4], hb1[2][4];
#pragma unroll
            for (int i = 0; i < 4; ++i) {
                hb0[0][i] = *(const float4*)(h0 + i * 4);
                hb1[0][i] = *(const float4*)(h1 + i * 4);
            }

#pragma unroll 2
            for (int rb = 0; rb < 8; ++rb) {
                const int cur = rb & 1, nxt = cur ^ 1;
                if (rb < 7) {
#pragma unroll
                    for (int i = 0; i < 4; ++i) {
                        hb0[nxt][i] = *(const float4*)(h0 + (rb + 1) * 16 + i * 4);
                        hb1[nxt][i] = *(const float4*)(h1 + (rb + 1) * 16 + i * 4);
                    }
                }
                const float* wb = wb_base + (size_t)(rb * 16) * 48;
                const float* hc0 = (const float*)hb0[cur];
                const float* hc1 = (const float*)hb1[cur];
#pragma unroll
                for (int k = 0; k < 16; ++k) {
                    const float* wp = wb + k * 48;
                    ulonglong2 wz = *(const ulonglong2*)(wp);
                    ulonglong2 wr = *(const ulonglong2*)(wp + 16);
                    ulonglong2 we = *(const ulonglong2*)(wp + 32);
                    u64t h0p = pack2(hc0[k], hc0[k]);
                    u64t h1p = pack2(hc1[k], hc1[k]);
                    fma2(acc[0], h0p, wz.x);  fma2(acc[1], h0p, wz.y);
                    fma2(acc[2], h0p, wr.x);  fma2(acc[3], h0p, wr.y);
                    fma2(acc[4], h0p, we.x);  fma2(acc[5], h0p, we.y);
                    fma2(acc[6], h1p, wz.x);  fma2(acc[7], h1p, wz.y);
                    fma2(acc[8], h1p, wr.x);  fma2(acc[9], h1p, wr.y);
                    fma2(acc[10], h1p, we.x); fma2(acc[11], h1p, we.y);
                }
            }

            // unpack accumulators: s[g*8 + r*4 + c]
            float s[24];
#pragma unroll
            for (int r = 0; r < 2; ++r)
#pragma unroll
                for (int g = 0; g < 3; ++g)
#pragma unroll
                    for (int ch = 0; ch < 2; ++ch)
                        unpack2(acc[r * 6 + g * 2 + ch],
                                s[g * 8 + r * 4 + 2 * ch],
                                s[g * 8 + r * 4 + 2 * ch + 1]);

            // ---- 2-stage tree reduction over 8 K-octants ----
            if (kq >= 4) {
                float* p = scr + (size_t)((kq - 4) * 64 + local) * SCR_STRIDE;
#pragma unroll
                for (int i = 0; i < 24; ++i) p[i] = s[i];
            }
            __syncthreads();
            if (kq < 4) {
                float* p = scr + (size_t)(kq * 64 + local) * SCR_STRIDE;
#pragma unroll
                for (int i = 0; i < 24; ++i) p[i] += s[i];
            }
        }
        __syncthreads();

        // ---- gate phase: one output per thread ----
        {
            float sz = 0.0f, sr = 0.0f, se = 0.0f;
            if (t > 0) {
#pragma unroll
                for (int q = 0; q < 4; ++q) {
                    const float* p = scr + (size_t)(q * 64 + glocal) * SCR_STRIDE
                                   + gr_ * 4 + gc_;
                    sz += p[0];
                    sr += p[8];
                    se += p[16];
                }
            }
            float hn = gate_fn(gz + sz, grv + sr, gev, se, hov);
            out[((size_t)(m0 + gm) * SS + t) * HH + jbase + gj] = hn;
        }

        // ---- grid-wide barrier ----
        __threadfence();
        __syncthreads();
        if (tid == 0) {
            unsigned int my = g_gen;
            unsigned int old = atomicAdd(&g_count, 1u);
            if (old == NBLOCKS - 1) {
                atomicExch(&g_count, 0u);
                __threadfence();
                g_gen = my + 1u;
            } else {
                while (g_gen == my) { __nanosleep(32); }
            }
            __threadfence();
        }
        __syncthreads();
    }

    // h_last = hidden_seq[:, S-1, :]
    {
        int idx = bid * NT + tid;              // 0..65535
        int b = idx >> 10, j = idx & 1023;
        out[(size_t)BB * SS * HH + idx] =
            out[((size_t)b * SS + (SS - 1)) * HH + j];
    }
}

// ---------------------------------------------------------------------------
extern "C" void kernel_launch(void* const* d_in, const int* in_sizes, int n_in,
                              void* d_out, int out_size) {
    const float* x    = (const float*)d_in[0];  // [64,512,512]
    const float* wih  = (const float*)d_in[1];  // [512,3072]
    const float* whh  = (const float*)d_in[2];  // [1024,3072]
    const float* bias = (const float*)d_in[3];  // [3072]
    float* out = (float*)d_out;

    (void)in_sizes; (void)n_in; (void)out_size;

    dim3 g1(G3 / 128, (BB * SS) / 128);
    gemm_ih<<<g1, 256>>>(x, wih, bias);

    const int scan_smem = (WSM_FLOATS + 4 * 64 * SCR_STRIDE) * (int)sizeof(float); // 222208 B
    cudaFuncSetAttribute(gru_scan, cudaFuncAttributeMaxDynamicSharedMemorySize, scan_smem);
    gru_scan<<<NBLOCKS, NT, scan_smem>>>(whh, out);
}

// round 7
// speedup vs baseline: 1.6655x; 1.6655x over previous
#include <cuda_runtime.h>
#include <math.h>

#define BB 64
#define SS 512
#define FF 512
#define HH 1024
#define G3 3072
#define NBLOCKS 128
#define NT 512
#define WSM_FLOATS (1024 * 48)      // resident W slice: [k=1024][48 gate-cols]
#define SCR_STRIDE 25               // reduction scratch stride (floats)
#define HT_BUF 65536                // 1024*64 floats per hT phase buffer

// Scratch: input-side gates gx = x @ W_ih + bias : [B*S, 3H] fp32
__device__ float g_gx[(size_t)BB * SS * G3];
// Transposed h mirror, double-buffered: g_hT[t&1][j (1024)][b (64)]
__device__ float g_hT[2 * HT_BUF];

// Software grid barrier (generation counter — replay-safe)
__device__ unsigned int g_count = 0;
__device__ volatile unsigned int g_gen = 0;

typedef unsigned long long u64t;

// ---------------- f32x2 packed-FMA helpers ----------------
__device__ __forceinline__ u64t pack2(float lo, float hi) {
    u64t r; asm("mov.b64 %0, {%1, %2};" : "=l"(r) : "f"(lo), "f"(hi)); return r;
}
__device__ __forceinline__ void unpack2(u64t v, float& lo, float& hi) {
    asm("mov.b64 {%0, %1}, %2;" : "=f"(lo), "=f"(hi) : "l"(v));
}
__device__ __forceinline__ void fma2(u64t& d, u64t a, u64t b) {
    asm("fma.rn.f32x2 %0, %1, %2, %0;" : "+l"(d) : "l"(a), "l"(b));
}

// ---------------- cp.async helpers ----------------
__device__ __forceinline__ void cp16(unsigned int dst, const void* src) {
    asm volatile("cp.async.ca.shared.global [%0], [%1], 16;" :: "r"(dst), "l"(src) : "memory");
}
__device__ __forceinline__ void cp_commit() { asm volatile("cp.async.commit_group;" ::: "memory"); }
template<int N> __device__ __forceinline__ void cp_wait() {
    asm volatile("cp.async.wait_group %0;" :: "n"(N) : "memory");
}
__device__ __forceinline__ unsigned int smem_u32(const void* p) {
    return (unsigned int)__cvta_generic_to_shared(p);
}

__device__ __forceinline__ float gate_fn(float az, float ar, float ge, float ae, float ho) {
    float z   = 1.0f / (1.0f + expf(-az));
    float r   = 1.0f / (1.0f + expf(-ar));
    float eta = tanhf(ge + r * tanhf(ae));
    return z * ho + (1.0f - z) * eta;
}

// ---------------------------------------------------------------------------
// Kernel 1: input GEMM  g_gx = x @ W_ih + bias.  M=32768, K=512, N=3072.
// ---------------------------------------------------------------------------
__global__ __launch_bounds__(256, 2) void gemm_ih(const float* __restrict__ A,
                                                  const float* __restrict__ Bw,
                                                  const float* __restrict__ bias) {
    __shared__ float As[16][132];
    __shared__ float Bs[16][128];

    const int K = FF, N = G3;
    const int bm = blockIdx.y * 128;
    const int bn = blockIdx.x * 128;
    const int tid = threadIdx.x;
    const int tr = tid >> 4;
    const int tc = tid & 15;

    u64t acc2[8][4];
#pragma unroll
    for (int i = 0; i < 8; ++i)
#pragma unroll
        for (int j = 0; j < 4; ++j) acc2[i][j] = 0ULL;

    for (int k0 = 0; k0 < K; k0 += 16) {
#pragma unroll
        for (int i = 0; i < 2; ++i) {
            int f = tid + i * 256;
            int ar = f >> 2, ac4 = f & 3;
            float4 av = *(const float4*)(A + (size_t)(bm + ar) * K + k0 + ac4 * 4);
            As[ac4 * 4 + 0][ar] = av.x;
            As[ac4 * 4 + 1][ar] = av.y;
            As[ac4 * 4 + 2][ar] = av.z;
            As[ac4 * 4 + 3][ar] = av.w;
            int br = f >> 5, bc4 = f & 31;
            *(float4*)(&Bs[br][bc4 * 4]) =
                *(const float4*)(Bw + (size_t)(k0 + br) * N + bn + bc4 * 4);
        }
        __syncthreads();
#pragma unroll
        for (int kk = 0; kk < 16; ++kk) {
            float a[8];
            *(float4*)(a)     = *(const float4*)(&As[kk][tr * 8]);
            *(float4*)(a + 4) = *(const float4*)(&As[kk][tr * 8 + 4]);
            ulonglong2 bq0 = *(const ulonglong2*)(&Bs[kk][tc * 8]);
            ulonglong2 bq1 = *(const ulonglong2*)(&Bs[kk][tc * 8 + 4]);
#pragma unroll
            for (int i = 0; i < 8; ++i) {
                u64t ai = pack2(a[i], a[i]);
                fma2(acc2[i][0], ai, bq0.x);
                fma2(acc2[i][1], ai, bq0.y);
                fma2(acc2[i][2], ai, bq1.x);
                fma2(acc2[i][3], ai, bq1.y);
            }
        }
        __syncthreads();
    }

#pragma unroll
    for (int i = 0; i < 8; ++i) {
        int row = bm + tr * 8 + i;
        float o[8];
        unpack2(acc2[i][0], o[0], o[1]);
        unpack2(acc2[i][1], o[2], o[3]);
        unpack2(acc2[i][2], o[4], o[5]);
        unpack2(acc2[i][3], o[6], o[7]);
#pragma unroll
        for (int j = 0; j < 8; j += 4) {
            int col = bn + tc * 8 + j;
            float4 bv = *(const float4*)(bias + col);
            float4 ov;
            ov.x = o[j + 0] + bv.x;
            ov.y = o[j + 1] + bv.y;
            ov.z = o[j + 2] + bv.z;
            ov.w = o[j + 3] + bv.w;
            *(float4*)(g_gx + (size_t)row * N + col) = ov;
        }
    }
}

// ---------------------------------------------------------------------------
// Kernel 2: persistent GRU scan. 128 CTAs x 512 threads, 512 steps.
//   W_hh slice [1024 x 48] resident in smem (loaded once).
//   h_{t-1} read from transposed mirror g_hT[j][b] -> 1-line coalesced LDG.128.
//   Thread tile: 4 rows x 2 cols/gate x 128 k (8-way K split). f32x2 FMA.
// ---------------------------------------------------------------------------
__global__ __launch_bounds__(NT, 1) void gru_scan(const float* __restrict__ whh,
                                                  float* __restrict__ out) {
    extern __shared__ float smem[];
    float* wsm = smem;                 // [1024][48]
    float* scr = smem + WSM_FLOATS;    // [4][64][SCR_STRIDE]

    const int bid = blockIdx.x;
    const int mt = bid >> 6;                // 0..1  batch half
    const int jt = bid & 63;                // 0..63 hidden col tile
    const int m0 = mt * 32;
    const int jbase = jt * 16;
    const int tid = threadIdx.x;
    const int kq = tid >> 6;                // 0..7 K octant (128 k each)
    const int local = tid & 63;
    const int mp = local & 7;               // rows 4mp..4mp+3 (of 32)
    const int jq = local >> 3;              // 0..7 -> cols {2jq, 2jq+1} per gate

    // ---- one-time W_hh slice load: whh[k][g*1024 + jbase + c] -> wsm[k][g*16 + c]
    {
        const unsigned int wsu = smem_u32(wsm);
#pragma unroll
        for (int i = 0; i < 24; ++i) {
            int idx = tid + NT * i;              // 0..12287
            int k = idx / 12;
            int sub = idx - k * 12;
            int g = sub >> 2, c4 = sub & 3;
            cp16(wsu + (unsigned)(k * 48 + g * 16 + c4 * 4) * 4u,
                 whh + (size_t)k * G3 + g * HH + jbase + c4 * 4);
        }
        cp_commit();
        cp_wait<0>();
        __syncthreads();
    }

    // gate-phase mapping: one output per thread
    const int gm = tid >> 4;                // 0..31 local row
    const int gj = tid & 15;                // 0..15 local col
    const int glocal = (gj >> 1) * 8 + (gm >> 2);
    const int gpidx = (gm & 3) * 6 + (gj & 1);  // + 2*g selects gate

    const float* wb_base = wsm + (size_t)(kq * 128) * 48 + jq * 2;

    for (int t = 0; t < SS; ++t) {
        // ---- prefetch gate-phase inputs (independent of this step's compute) ----
        const float* gp = g_gx + ((size_t)(m0 + gm) * SS + t) * G3 + jbase + gj;
        float gz = gp[0], grv = gp[HH], gev = gp[2 * HH];
        float hov = 0.0f;
        if (t > 0)
            hov = out[((size_t)(m0 + gm) * SS + (t - 1)) * HH + jbase + gj];

        if (t > 0) {
            // h from transposed mirror: 8 lanes x 16B = one 128B line per warp-LDG
            const float* hb = g_hT + (size_t)((t - 1) & 1) * HT_BUF
                            + (size_t)(kq * 128) * 64 + m0 + 4 * mp;

            u64t acc[12];
#pragma unroll
            for (int i = 0; i < 12; ++i) acc[i] = 0ULL;

            float4 hreg[2][4];
#pragma unroll
            for (int i = 0; i < 4; ++i)
                hreg[0][i] = *(const float4*)(hb + (size_t)i * 64);

#pragma unroll 2
            for (int jb = 0; jb < 128; jb += 4) {
                const int cur = (jb >> 2) & 1, nxt = cur ^ 1;
                if (jb < 124) {
#pragma unroll
                    for (int i = 0; i < 4; ++i)
                        hreg[nxt][i] = *(const float4*)(hb + (size_t)(jb + 4 + i) * 64);
                }
#pragma unroll
                for (int i = 0; i < 4; ++i) {
                    const float* wp = wb_base + (size_t)(jb + i) * 48;
                    u64t wz = *(const u64t*)(wp);
                    u64t wr = *(const u64t*)(wp + 16);
                    u64t we = *(const u64t*)(wp + 32);
                    float4 h = hreg[cur][i];
                    u64t h0 = pack2(h.x, h.x);
                    u64t h1 = pack2(h.y, h.y);
                    u64t h2 = pack2(h.z, h.z);
                    u64t h3 = pack2(h.w, h.w);
                    fma2(acc[0], h0, wz);  fma2(acc[1], h0, wr);  fma2(acc[2], h0, we);
                    fma2(acc[3], h1, wz);  fma2(acc[4], h1, wr);  fma2(acc[5], h1, we);
                    fma2(acc[6], h2, wz);  fma2(acc[7], h2, wr);  fma2(acc[8], h2, we);
                    fma2(acc[9], h3, wz);  fma2(acc[10], h3, wr); fma2(acc[11], h3, we);
                }
            }

            // unpack: s[r*6 + g*2 + c] for row 4mp+r, gate g, col 2jq+c
            float s[24];
#pragma unroll
            for (int r = 0; r < 4; ++r)
#pragma unroll
                for (int g = 0; g < 3; ++g)
                    unpack2(acc[r * 3 + g], s[r * 6 + g * 2], s[r * 6 + g * 2 + 1]);

            // ---- 2-stage tree reduction over 8 K-octants ----
            if (kq >= 4) {
                float* p = scr + (size_t)((kq - 4) * 64 + local) * SCR_STRIDE;
#pragma unroll
                for (int i = 0; i < 24; ++i) p[i] = s[i];
            }
            __syncthreads();
            if (kq < 4) {
                float* p = scr + (size_t)(kq * 64 + local) * SCR_STRIDE;
#pragma unroll
                for (int i = 0; i < 24; ++i) p[i] += s[i];
            }
        }
        __syncthreads();

        // ---- gate phase: one output per thread ----
        {
            float sz = 0.0f, sr = 0.0f, se = 0.0f;
            if (t > 0) {
#pragma unroll
                for (int q = 0; q < 4; ++q) {
                    const float* p = scr + (size_t)(q * 64 + glocal) * SCR_STRIDE + gpidx;
                    sz += p[0];
                    sr += p[2];
                    se += p[4];
                }
            }
            float hn = gate_fn(gz + sz, grv + sr, gev, se, hov);
            out[((size_t)(m0 + gm) * SS + t) * HH + jbase + gj] = hn;
            g_hT[(size_t)(t & 1) * HT_BUF + (size_t)(jbase + gj) * 64 + m0 + gm] = hn;
        }

        // ---- grid-wide barrier ----
        __threadfence();
        __syncthreads();
        if (tid == 0) {
            unsigned int my = g_gen;
            unsigned int old = atomicAdd(&g_count, 1u);
            if (old == NBLOCKS - 1) {
                atomicExch(&g_count, 0u);
                __threadfence();
                g_gen = my + 1u;
            } else {
                while (g_gen == my) { __nanosleep(32); }
            }
            __threadfence();
        }
        __syncthreads();
    }

    // h_last = hidden_seq[:, S-1, :]
    {
        int idx = bid * NT + tid;              // 0..65535
        int b = idx >> 10, j = idx & 1023;
        out[(size_t)BB * SS * HH + idx] =
            out[((size_t)b * SS + (SS - 1)) * HH + j];
    }
}

// ---------------------------------------------------------------------------
extern "C" void kernel_launch(void* const* d_in, const int* in_sizes, int n_in,
                              void* d_out, int out_size) {
    const float* x    = (const float*)d_in[0];  // [64,512,512]
    const float* wih  = (const float*)d_in[1];  // [512,3072]
    const float* whh  = (const float*)d_in[2];  // [1024,3072]
    const float* bias = (const float*)d_in[3];  // [3072]
    float* out = (float*)d_out;

    (void)in_sizes; (void)n_in; (void)out_size;

    dim3 g1(G3 / 128, (BB * SS) / 128);
    gemm_ih<<<g1, 256>>>(x, wih, bias);

    const int scan_smem = (WSM_FLOATS + 4 * 64 * SCR_STRIDE) * (int)sizeof(float); // 222208 B
    cudaFuncSetAttribute(gru_scan, cudaFuncAttributeMaxDynamicSharedMemorySize, scan_smem);
    gru_scan<<<NBLOCKS, NT, scan_smem>>>(whh, out);
}